// round 1
// baseline (speedup 1.0000x reference)
#include <cuda_runtime.h>
#include <math.h>

#define BATCH 8192
#define DTOT  4611
#define TI 128
#define TJ 128
#define KB 16

// ---------------- scratch (static device globals: no allocation allowed) ---
__device__ float    g_G[(size_t)BATCH * DTOT];   // generated weights, 151 MB
__device__ float    g_rnG[BATCH];                // |G_j|^2
__device__ float    g_rnP[BATCH];                // |prior_i|^2
__device__ unsigned g_minP[BATCH];               // monotone-key min over i of rnP_i - 2 P_i.G_j
__device__ unsigned g_minG[BATCH];               // same for G-G (diag excluded)
__device__ float    g_recon[BATCH];              // per-sample recon

// monotone float<->uint key so atomicMin(uint) == min(float), exactly & deterministically
__device__ __forceinline__ unsigned fkey(float f) {
    unsigned u = __float_as_uint(f);
    return (u & 0x80000000u) ? ~u : (u | 0x80000000u);
}
__device__ __forceinline__ float funkey(unsigned k) {
    unsigned u = (k & 0x80000000u) ? (k ^ 0x80000000u) : ~k;
    return __uint_as_float(u);
}

// ---------------- phase A: build G = concat(n@W + b) -----------------------
__global__ void build_G_kernel(const float* __restrict__ n,
                               const float* __restrict__ w1W, const float* __restrict__ w1b,
                               const float* __restrict__ b1W, const float* __restrict__ b1b,
                               const float* __restrict__ w2W, const float* __restrict__ w2b,
                               const float* __restrict__ b2W, const float* __restrict__ b2b,
                               const float* __restrict__ w3W, const float* __restrict__ w3b,
                               const float* __restrict__ b3W, const float* __restrict__ b3b)
{
    __shared__ float ns[25];
    const int b = blockIdx.y;
    if (threadIdx.x < 25) ns[threadIdx.x] = n[b * 25 + threadIdx.x];
    __syncthreads();
    const int c = blockIdx.x * 256 + threadIdx.x;
    if (c >= DTOT) return;

    const float* W; const float* bias; int local, width;
    if      (c < 192)  { W = w1W; bias = w1b; local = c;        width = 192;  }
    else if (c < 256)  { W = b1W; bias = b1b; local = c - 192;  width = 64;   }
    else if (c < 4352) { W = w2W; bias = w2b; local = c - 256;  width = 4096; }
    else if (c < 4416) { W = b2W; bias = b2b; local = c - 4352; width = 64;   }
    else if (c < 4608) { W = w3W; bias = w3b; local = c - 4416; width = 192;  }
    else               { W = b3W; bias = b3b; local = c - 4608; width = 3;    }

    float acc = 0.f;
    #pragma unroll
    for (int k = 0; k < 25; k++) acc += ns[k] * W[k * width + local];
    acc += bias[local];
    g_G[(long)b * DTOT + c] = acc;
}

// ---------------- row squared-norms (mode 0: prior -> rnP, mode 1: G -> rnG)
__global__ void row_norm_kernel(const float* __restrict__ prior, int mode)
{
    const float* X  = mode ? g_G  : prior;
    float*       rn = mode ? g_rnG : g_rnP;
    const int row = blockIdx.x;
    const float* p = X + (long)row * DTOT;
    float s = 0.f;
    for (int k = threadIdx.x; k < DTOT; k += 256) { float v = p[k]; s += v * v; }
    __shared__ float sm[256];
    sm[threadIdx.x] = s;
    __syncthreads();
    for (int off = 128; off > 0; off >>= 1) {
        if (threadIdx.x < off) sm[threadIdx.x] += sm[threadIdx.x + off];
        __syncthreads();
    }
    if (threadIdx.x == 0) rn[row] = sm[0];
}

__global__ void init_min_kernel()
{
    int t = blockIdx.x * 256 + threadIdx.x;
    if (t < BATCH) { g_minP[t] = 0xFFFFFFFFu; g_minG[t] = 0xFFFFFFFFu; }
}

// ---------------- phase B: decode MLP, z_hat + per-sample recon ------------
__global__ void decode_kernel(const float* __restrict__ z,
                              const float* __restrict__ znext,
                              float* __restrict__ out)
{
    const int b = blockIdx.x;
    const float* g = g_G + (long)b * DTOT;
    const int i = threadIdx.x;             // 64 threads
    __shared__ float h1[64], h2[64], zh[3];

    const float z0 = z[b * 3], z1 = z[b * 3 + 1], z2 = z[b * 3 + 2];
    float a = g[i * 3] * z0 + g[i * 3 + 1] * z1 + g[i * 3 + 2] * z2 + g[192 + i];
    h1[i] = (a > 0.f) ? a : expm1f(a);
    __syncthreads();

    const float* w2 = g + 256 + i * 64;
    float s = 0.f;
    #pragma unroll 8
    for (int j = 0; j < 64; j++) s += w2[j] * h1[j];
    s += g[4352 + i];
    h2[i] = (s > 0.f) ? s : expm1f(s);
    __syncthreads();

    if (i < 3) {
        const float* w3 = g + 4416 + i * 64;
        float s3 = 0.f;
        #pragma unroll 8
        for (int j = 0; j < 64; j++) s3 += w3[j] * h2[j];
        s3 += g[4608 + i];
        out[2 + b * 3 + i] = s3;
        zh[i] = s3;
    }
    __syncthreads();
    if (i == 0) {
        float d0 = zh[0] - znext[b * 3];
        float d1 = zh[1] - znext[b * 3 + 1];
        float d2 = zh[2] - znext[b * 3 + 2];
        g_recon[b] = d0 * d0 + d1 * d1 + d2 * d2;
    }
}

// ---------------- phase C: fused GEMM + column-min ------------------------
// Computes for each column j: min over i of (rnA[i] - 2 * A_i . G_j),
// atomically folded into colmin[j] as a monotone uint key.
// pass 0: A = prior; pass 1: A = G with diagonal excluded.
__global__ __launch_bounds__(256, 2)
void min_gemm_kernel(const float* __restrict__ prior, int pass)
{
    const float* __restrict__ A   = pass ? g_G  : prior;
    const float* __restrict__ Bm  = g_G;
    const float* __restrict__ rnA = pass ? g_rnG : g_rnP;
    unsigned* colmin              = pass ? g_minG : g_minP;

    __shared__ __align__(16) float As[KB][TI + 4];
    __shared__ __align__(16) float Bs[KB][TJ + 4];
    __shared__ float red[16][TJ];

    const int tid = threadIdx.x;
    const int ty = tid >> 4;          // 0..15, rows
    const int tx = tid & 15;          // 0..15, cols
    const long i0 = (long)blockIdx.y * TI;
    const long j0 = (long)blockIdx.x * TJ;

    // 8x8 fp32 accumulators held as f32x2 pairs (columns paired)
    unsigned long long acc[8][4];
    #pragma unroll
    for (int r = 0; r < 8; r++)
        #pragma unroll
        for (int p = 0; p < 4; p++) acc[r][p] = 0ULL;

    for (int k0 = 0; k0 < DTOT; k0 += KB) {
        // cooperative load (zero-pad K remainder)
        #pragma unroll
        for (int s = 0; s < (TI * KB) / 256; s++) {
            int idx = s * 256 + tid;
            int r = idx >> 4;
            int k = idx & 15;
            int gk = k0 + k;
            float av = 0.f, bv = 0.f;
            if (gk < DTOT) {
                av = A[(i0 + r) * (long)DTOT + gk];
                bv = Bm[(j0 + r) * (long)DTOT + gk];
            }
            As[k][r] = av;
            Bs[k][r] = bv;
        }
        __syncthreads();

        #pragma unroll
        for (int k = 0; k < KB; k++) {
            const float4 a0 = *reinterpret_cast<const float4*>(&As[k][ty * 8]);
            const float4 a1 = *reinterpret_cast<const float4*>(&As[k][ty * 8 + 4]);
            const float4 b0 = *reinterpret_cast<const float4*>(&Bs[k][tx * 8]);
            const float4 b1 = *reinterpret_cast<const float4*>(&Bs[k][tx * 8 + 4]);
            unsigned long long bb[4];
            asm("mov.b64 %0, {%1, %2};" : "=l"(bb[0]) : "f"(b0.x), "f"(b0.y));
            asm("mov.b64 %0, {%1, %2};" : "=l"(bb[1]) : "f"(b0.z), "f"(b0.w));
            asm("mov.b64 %0, {%1, %2};" : "=l"(bb[2]) : "f"(b1.x), "f"(b1.y));
            asm("mov.b64 %0, {%1, %2};" : "=l"(bb[3]) : "f"(b1.z), "f"(b1.w));
            const float av8[8] = {a0.x, a0.y, a0.z, a0.w, a1.x, a1.y, a1.z, a1.w};
            #pragma unroll
            for (int r = 0; r < 8; r++) {
                unsigned long long aa;
                asm("mov.b64 %0, {%1, %1};" : "=l"(aa) : "f"(av8[r]));
                #pragma unroll
                for (int p = 0; p < 4; p++)
                    asm("fma.rn.f32x2 %0, %1, %2, %0;"
                        : "+l"(acc[r][p]) : "l"(aa), "l"(bb[p]));
            }
        }
        __syncthreads();
    }

    // epilogue: v = rnA[i] - 2*dot, min over the 8 local rows
    float vmin[8];
    #pragma unroll
    for (int c = 0; c < 8; c++) vmin[c] = 1e30f;
    #pragma unroll
    for (int r = 0; r < 8; r++) {
        const long ig = i0 + ty * 8 + r;
        const float rn = rnA[ig];
        #pragma unroll
        for (int p = 0; p < 4; p++) {
            float lo, hi;
            asm("mov.b64 {%0, %1}, %2;" : "=f"(lo), "=f"(hi) : "l"(acc[r][p]));
            float v0 = rn - 2.f * lo;
            float v1 = rn - 2.f * hi;
            const long jg = j0 + tx * 8 + 2 * p;
            if (pass && ig == jg)     v0 = 1e30f;   // exclude diagonal
            if (pass && ig == jg + 1) v1 = 1e30f;
            vmin[2 * p]     = fminf(vmin[2 * p], v0);
            vmin[2 * p + 1] = fminf(vmin[2 * p + 1], v1);
        }
    }
    #pragma unroll
    for (int c = 0; c < 8; c++) red[ty][tx * 8 + c] = vmin[c];
    __syncthreads();
    if (tid < TJ) {
        float m = 1e30f;
        #pragma unroll
        for (int t = 0; t < 16; t++) m = fminf(m, red[t][tid]);
        atomicMin(&colmin[j0 + tid], fkey(m));
    }
}

// ---------------- phase D: final scalar reductions -------------------------
__global__ void finalize_kernel(float* __restrict__ out)
{
    __shared__ float s1[1024], s2[1024];
    const int t = threadIdx.x;
    float rsum = 0.f, ksum = 0.f;
    for (int j = t; j < BATCH; j += 1024) {
        rsum += g_recon[j];
        float rn = g_rnG[j];
        float wp = sqrtf(fmaxf(funkey(g_minP[j]) + rn, 0.f) + 1e-8f);
        float ww = sqrtf(fmaxf(funkey(g_minG[j]) + rn, 0.f) + 1e-8f);
        ksum += logf(wp / (ww + 1e-8f) + 1e-8f);
    }
    s1[t] = rsum; s2[t] = ksum;
    __syncthreads();
    for (int off = 512; off > 0; off >>= 1) {
        if (t < off) { s1[t] += s1[t + off]; s2[t] += s2[t + off]; }
        __syncthreads();
    }
    if (t == 0) {
        out[0] = s1[0] / (float)BATCH;                                    // recon
        out[1] = s2[0] / (float)BATCH * (float)DTOT
               + logf((float)BATCH / (float)(BATCH - 1));                  // kl
    }
}

// ---------------- launch ----------------------------------------------------
extern "C" void kernel_launch(void* const* d_in, const int* in_sizes, int n_in,
                              void* d_out, int out_size)
{
    (void)in_sizes; (void)n_in; (void)out_size;
    const float* z     = (const float*)d_in[0];
    const float* znext = (const float*)d_in[1];
    const float* n     = (const float*)d_in[2];
    const float* prior = (const float*)d_in[3];
    const float* w1W = (const float*)d_in[4];  const float* w1b = (const float*)d_in[5];
    const float* b1W = (const float*)d_in[6];  const float* b1b = (const float*)d_in[7];
    const float* w2W = (const float*)d_in[8];  const float* w2b = (const float*)d_in[9];
    const float* b2W = (const float*)d_in[10]; const float* b2b = (const float*)d_in[11];
    const float* w3W = (const float*)d_in[12]; const float* w3b = (const float*)d_in[13];
    const float* b3W = (const float*)d_in[14]; const float* b3b = (const float*)d_in[15];
    float* out = (float*)d_out;

    // A: hypernetwork output G
    build_G_kernel<<<dim3((DTOT + 255) / 256, BATCH), 256>>>(
        n, w1W, w1b, b1W, b1b, w2W, w2b, b2W, b2b, w3W, w3b, b3W, b3b);

    // norms + min init
    row_norm_kernel<<<BATCH, 256>>>(prior, 0);
    row_norm_kernel<<<BATCH, 256>>>(prior, 1);
    init_min_kernel<<<(BATCH + 255) / 256, 256>>>();

    // B: decode + recon + z_hat
    decode_kernel<<<BATCH, 64>>>(z, znext, out);

    // C: the two heavy fused GEMM+min passes
    min_gemm_kernel<<<dim3(BATCH / TJ, BATCH / TI), 256>>>(prior, 0);
    min_gemm_kernel<<<dim3(BATCH / TJ, BATCH / TI), 256>>>(prior, 1);

    // D: scalars
    finalize_kernel<<<1, 1024>>>(out);
}

// round 3
// speedup vs baseline: 7.2987x; 7.2987x over previous
#include <cuda_runtime.h>
#include <cuda_fp16.h>
#include <math.h>
#include <stdint.h>

#define BATCH 8192
#define DTOT  4611
#define KPAD  4672              // 73 * 64, zero-padded tail
#define NCHUNK (KPAD / 64)      // 73
#define TM 128
#define TN 256
#define TK 64
#define STAGE_BYTES 49152       // A 16KB + B 32KB
#define SMEM_TOTAL (3 * STAGE_BYTES)

// ---------------- static device scratch -------------------------------------
__device__ float  g_Gf[(size_t)BATCH * DTOT];   // exact fp32 G (decode/norms)
__device__ __half g_Gh[(size_t)BATCH * KPAD];   // fp16 G for MMA
__device__ __half g_Ph[(size_t)BATCH * KPAD];   // fp16 prior for MMA
__device__ float    g_rnG[BATCH];
__device__ float    g_rnP[BATCH];
__device__ unsigned g_minP[BATCH];
__device__ unsigned g_minG[BATCH];
__device__ float    g_recon[BATCH];

// monotone float<->uint key: atomicMin(uint) == min(float), exact+deterministic
__device__ __forceinline__ unsigned fkey(float f) {
    unsigned u = __float_as_uint(f);
    return (u & 0x80000000u) ? ~u : (u | 0x80000000u);
}
__device__ __forceinline__ float funkey(unsigned k) {
    unsigned u = (k & 0x80000000u) ? (k ^ 0x80000000u) : ~k;
    return __uint_as_float(u);
}

__device__ __forceinline__ uint32_t smem_u32(const void* p) {
    uint32_t a;
    asm("{ .reg .u64 t; cvta.to.shared.u64 t, %1; cvt.u32.u64 %0, t; }" : "=r"(a) : "l"(p));
    return a;
}

__device__ __forceinline__ void ldsm_x4(uint32_t& r0, uint32_t& r1, uint32_t& r2,
                                        uint32_t& r3, uint32_t addr) {
    asm volatile("ldmatrix.sync.aligned.m8n8.x4.shared.b16 {%0,%1,%2,%3}, [%4];"
                 : "=r"(r0), "=r"(r1), "=r"(r2), "=r"(r3) : "r"(addr));
}

__device__ __forceinline__ void mma16816(float* d, const uint32_t* a,
                                         uint32_t b0, uint32_t b1) {
    asm volatile("mma.sync.aligned.m16n8k16.row.col.f32.f16.f16.f32 "
                 "{%0,%1,%2,%3}, {%4,%5,%6,%7}, {%8,%9}, {%0,%1,%2,%3};"
                 : "+f"(d[0]), "+f"(d[1]), "+f"(d[2]), "+f"(d[3])
                 : "r"(a[0]), "r"(a[1]), "r"(a[2]), "r"(a[3]), "r"(b0), "r"(b1));
}

// ---------------- phase A: hypernetwork -> fp32 G + fp16 G ------------------
__global__ void build_G_kernel(const float* __restrict__ n,
                               const float* __restrict__ w1W, const float* __restrict__ w1b,
                               const float* __restrict__ b1W, const float* __restrict__ b1b,
                               const float* __restrict__ w2W, const float* __restrict__ w2b,
                               const float* __restrict__ b2W, const float* __restrict__ b2b,
                               const float* __restrict__ w3W, const float* __restrict__ w3b,
                               const float* __restrict__ b3W, const float* __restrict__ b3b)
{
    __shared__ float ns[25];
    const int b = blockIdx.y;
    if (threadIdx.x < 25) ns[threadIdx.x] = n[b * 25 + threadIdx.x];
    __syncthreads();
    const int c = blockIdx.x * 256 + threadIdx.x;
    if (c >= KPAD) return;

    float val = 0.f;
    if (c < DTOT) {
        const float* W; const float* bias; int local, width;
        if      (c < 192)  { W = w1W; bias = w1b; local = c;        width = 192;  }
        else if (c < 256)  { W = b1W; bias = b1b; local = c - 192;  width = 64;   }
        else if (c < 4352) { W = w2W; bias = w2b; local = c - 256;  width = 4096; }
        else if (c < 4416) { W = b2W; bias = b2b; local = c - 4352; width = 64;   }
        else if (c < 4608) { W = w3W; bias = w3b; local = c - 4416; width = 192;  }
        else               { W = b3W; bias = b3b; local = c - 4608; width = 3;    }
        float acc = 0.f;
        #pragma unroll
        for (int k = 0; k < 25; k++) acc += ns[k] * W[k * width + local];
        val = acc + bias[local];
        g_Gf[(long)b * DTOT + c] = val;
    }
    g_Gh[(long)b * KPAD + c] = __float2half_rn(val);
}

__global__ void split_prior_kernel(const float* __restrict__ prior)
{
    const int b = blockIdx.y;
    const int c = blockIdx.x * 256 + threadIdx.x;
    if (c >= KPAD) return;
    float val = (c < DTOT) ? prior[(long)b * DTOT + c] : 0.f;
    g_Ph[(long)b * KPAD + c] = __float2half_rn(val);
}

// row squared-norms; mode 0: prior, mode 1: G (both exact fp32)
__global__ void row_norm_kernel(const float* __restrict__ prior, int mode)
{
    const int row = blockIdx.x;
    const float* p = (mode ? g_Gf : prior) + (long)row * DTOT;
    float s = 0.f;
    for (int k = threadIdx.x; k < DTOT; k += 256) { float v = p[k]; s += v * v; }
    __shared__ float sm[256];
    sm[threadIdx.x] = s;
    __syncthreads();
    for (int off = 128; off > 0; off >>= 1) {
        if (threadIdx.x < off) sm[threadIdx.x] += sm[threadIdx.x + off];
        __syncthreads();
    }
    if (threadIdx.x == 0) { if (mode) g_rnG[row] = sm[0]; else g_rnP[row] = sm[0]; }
}

__global__ void init_min_kernel()
{
    int t = blockIdx.x * 256 + threadIdx.x;
    if (t < BATCH) { g_minP[t] = 0xFFFFFFFFu; g_minG[t] = 0xFFFFFFFFu; }
}

// ---------------- phase B: decode MLP (fp32 G) ------------------------------
__global__ void decode_kernel(const float* __restrict__ z,
                              const float* __restrict__ znext,
                              float* __restrict__ out)
{
    const int b = blockIdx.x;
    const float* g = g_Gf + (long)b * DTOT;
    const int i = threadIdx.x;             // 64 threads
    __shared__ float h1[64], h2[64], zh[3];

    const float z0 = z[b * 3], z1 = z[b * 3 + 1], z2 = z[b * 3 + 2];
    float a = g[i * 3] * z0 + g[i * 3 + 1] * z1 + g[i * 3 + 2] * z2 + g[192 + i];
    h1[i] = (a > 0.f) ? a : expm1f(a);
    __syncthreads();

    const float* w2 = g + 256 + i * 64;
    float s = 0.f;
    #pragma unroll 8
    for (int j = 0; j < 64; j++) s += w2[j] * h1[j];
    s += g[4352 + i];
    h2[i] = (s > 0.f) ? s : expm1f(s);
    __syncthreads();

    if (i < 3) {
        const float* w3 = g + 4416 + i * 64;
        float s3 = 0.f;
        #pragma unroll 8
        for (int j = 0; j < 64; j++) s3 += w3[j] * h2[j];
        s3 += g[4608 + i];
        out[2 + b * 3 + i] = s3;
        zh[i] = s3;
    }
    __syncthreads();
    if (i == 0) {
        float d0 = zh[0] - znext[b * 3];
        float d1 = zh[1] - znext[b * 3 + 1];
        float d2 = zh[2] - znext[b * 3 + 2];
        g_recon[b] = d0 * d0 + d1 * d1 + d2 * d2;
    }
}

// ---------------- phase C: HMMA fused GEMM + column-min ---------------------
// colmin[j] = min over i of (rnA[i] - 2 * A_i . G_j); pass1 excludes diagonal.
__device__ __forceinline__ void load_tile(uint32_t sbase, const __half* __restrict__ g,
                                          long row0, int k0, int nrows, int tid)
{
    const int nunits = nrows * 8;           // 16B units, 128B per row
    #pragma unroll 4
    for (int u = tid; u < nunits; u += 256) {
        const int r = u >> 3, un = u & 7;
        const int sw = un ^ (r & 7);
        const void* src = g + (row0 + r) * (long)KPAD + k0 + un * 8;
        asm volatile("cp.async.cg.shared.global [%0], [%1], 16;"
                     :: "r"(sbase + (uint32_t)(r * 128 + sw * 16)), "l"(src) : "memory");
    }
}

__global__ __launch_bounds__(256, 1)
void min_gemm_hmma_kernel(int pass)
{
    const __half* __restrict__ A  = pass ? g_Gh : g_Ph;
    const float* __restrict__ rnA = pass ? g_rnG : g_rnP;
    unsigned* colmin              = pass ? g_minG : g_minP;

    extern __shared__ char smem[];
    const uint32_t sb = smem_u32(smem);
    const int tid = threadIdx.x;
    const int lane = tid & 31;
    const int wid = tid >> 5;
    const int wm = wid >> 2;                 // 0..1  (M)
    const int wn = wid & 3;                  // 0..3  (N)
    const long i0 = (long)blockIdx.y * TM;
    const long j0 = (long)blockIdx.x * TN;

    float d[4][8][4];
    #pragma unroll
    for (int mi = 0; mi < 4; mi++)
        #pragma unroll
        for (int ni = 0; ni < 8; ni++)
            #pragma unroll
            for (int q = 0; q < 4; q++) d[mi][ni][q] = 0.f;

    // per-thread ldmatrix row bases
    int aoff[4], asw[4], boff[4], bsw[4];
    const int ahalf = (lane >> 4) & 1;       // A: bit4 -> k half
    const int bhalf = (lane >> 3) & 1;       // B: bit3 -> k half
    #pragma unroll
    for (int mi = 0; mi < 4; mi++) {
        int row = wm * 64 + mi * 16 + (lane & 7) + ((lane >> 3) & 1) * 8;
        aoff[mi] = row * 128; asw[mi] = row & 7;
    }
    #pragma unroll
    for (int nb = 0; nb < 4; nb++) {
        int row = wn * 64 + nb * 16 + (lane & 7) + ((lane >> 4) & 1) * 8;
        boff[nb] = row * 128; bsw[nb] = row & 7;
    }

    // prologue: chunks 0,1 into stages 0,1
    load_tile(sb,                  A,    i0, 0,  TM, tid);
    load_tile(sb + 16384,          g_Gh, j0, 0,  TN, tid);
    asm volatile("cp.async.commit_group;" ::: "memory");
    load_tile(sb + STAGE_BYTES,          A,    i0, TK, TM, tid);
    load_tile(sb + STAGE_BYTES + 16384,  g_Gh, j0, TK, TN, tid);
    asm volatile("cp.async.commit_group;" ::: "memory");

    int stage = 0, next = 2;
    for (int c = 0; c < NCHUNK; c++) {
        if (c + 2 < NCHUNK) {
            const uint32_t sn = sb + (uint32_t)next * STAGE_BYTES;
            load_tile(sn,         A,    i0, (c + 2) * TK, TM, tid);
            load_tile(sn + 16384, g_Gh, j0, (c + 2) * TK, TN, tid);
            asm volatile("cp.async.commit_group;" ::: "memory");
            asm volatile("cp.async.wait_group 2;" ::: "memory");
        } else if (c + 1 < NCHUNK) {
            asm volatile("cp.async.wait_group 1;" ::: "memory");
        } else {
            asm volatile("cp.async.wait_group 0;" ::: "memory");
        }
        __syncthreads();

        const uint32_t Ab = sb + (uint32_t)stage * STAGE_BYTES;
        const uint32_t Bb = Ab + 16384;

        #pragma unroll
        for (int ks = 0; ks < 4; ks++) {
            uint32_t a[4][4], b[4][4];
            #pragma unroll
            for (int mi = 0; mi < 4; mi++)
                ldsm_x4(a[mi][0], a[mi][1], a[mi][2], a[mi][3],
                        Ab + aoff[mi] + (uint32_t)(((ks * 2 + ahalf) ^ asw[mi]) * 16));
            #pragma unroll
            for (int nb = 0; nb < 4; nb++)
                ldsm_x4(b[nb][0], b[nb][1], b[nb][2], b[nb][3],
                        Bb + boff[nb] + (uint32_t)(((ks * 2 + bhalf) ^ bsw[nb]) * 16));
            #pragma unroll
            for (int mi = 0; mi < 4; mi++)
                #pragma unroll
                for (int nb = 0; nb < 4; nb++) {
                    mma16816(d[mi][nb * 2],     a[mi], b[nb][0], b[nb][1]);
                    mma16816(d[mi][nb * 2 + 1], a[mi], b[nb][2], b[nb][3]);
                }
        }
        __syncthreads();
        stage = (stage + 1) % 3;
        next  = (next + 1) % 3;
    }

    // epilogue: v = rnA[i] - 2*D, diag mask, min over i per column
    const int g = lane >> 2, tig = lane & 3;
    float cmin[8][2];
    #pragma unroll
    for (int ni = 0; ni < 8; ni++) { cmin[ni][0] = 1e30f; cmin[ni][1] = 1e30f; }

    #pragma unroll
    for (int mi = 0; mi < 4; mi++) {
        const long ig0 = i0 + wm * 64 + mi * 16 + g;
        const long ig1 = ig0 + 8;
        const float rn0 = rnA[ig0];
        const float rn1 = rnA[ig1];
        #pragma unroll
        for (int ni = 0; ni < 8; ni++) {
            float v0 = fmaf(-2.f, d[mi][ni][0], rn0);
            float v1 = fmaf(-2.f, d[mi][ni][1], rn0);
            float v2 = fmaf(-2.f, d[mi][ni][2], rn1);
            float v3 = fmaf(-2.f, d[mi][ni][3], rn1);
            if (pass) {
                const long jg = j0 + wn * 64 + ni * 8 + 2 * tig;
                if (ig0 == jg)     v0 = 1e30f;
                if (ig0 == jg + 1) v1 = 1e30f;
                if (ig1 == jg)     v2 = 1e30f;
                if (ig1 == jg + 1) v3 = 1e30f;
            }
            cmin[ni][0] = fminf(cmin[ni][0], fminf(v0, v2));
            cmin[ni][1] = fminf(cmin[ni][1], fminf(v1, v3));
        }
    }
    // reduce across g (lanes differing in bits 2..4)
    #pragma unroll
    for (int off = 4; off <= 16; off <<= 1)
        #pragma unroll
        for (int ni = 0; ni < 8; ni++) {
            cmin[ni][0] = fminf(cmin[ni][0], __shfl_xor_sync(0xFFFFFFFFu, cmin[ni][0], off));
            cmin[ni][1] = fminf(cmin[ni][1], __shfl_xor_sync(0xFFFFFFFFu, cmin[ni][1], off));
        }

    float* buf = (float*)smem;   // [2][256]
    if (lane < 4) {
        #pragma unroll
        for (int ni = 0; ni < 8; ni++) {
            const int col = wn * 64 + ni * 8 + 2 * lane;
            buf[wm * 256 + col]     = cmin[ni][0];
            buf[wm * 256 + col + 1] = cmin[ni][1];
        }
    }
    __syncthreads();
    {
        const float m = fminf(buf[tid], buf[256 + tid]);
        atomicMin(&colmin[j0 + tid], fkey(m));
    }
}

// ---------------- phase D: final scalar reductions ---------------------------
__global__ void finalize_kernel(float* __restrict__ out)
{
    __shared__ float s1[1024], s2[1024];
    const int t = threadIdx.x;
    float rsum = 0.f, ksum = 0.f;
    for (int j = t; j < BATCH; j += 1024) {
        rsum += g_recon[j];
        float rn = g_rnG[j];
        float wp = sqrtf(fmaxf(funkey(g_minP[j]) + rn, 0.f) + 1e-8f);
        float ww = sqrtf(fmaxf(funkey(g_minG[j]) + rn, 0.f) + 1e-8f);
        ksum += logf(wp / (ww + 1e-8f) + 1e-8f);
    }
    s1[t] = rsum; s2[t] = ksum;
    __syncthreads();
    for (int off = 512; off > 0; off >>= 1) {
        if (t < off) { s1[t] += s1[t + off]; s2[t] += s2[t + off]; }
        __syncthreads();
    }
    if (t == 0) {
        out[0] = s1[0] / (float)BATCH;
        out[1] = s2[0] / (float)BATCH * (float)DTOT
               + logf((float)BATCH / (float)(BATCH - 1));
    }
}

// ---------------- launch ------------------------------------------------------
extern "C" void kernel_launch(void* const* d_in, const int* in_sizes, int n_in,
                              void* d_out, int out_size)
{
    (void)in_sizes; (void)n_in; (void)out_size;
    const float* z     = (const float*)d_in[0];
    const float* znext = (const float*)d_in[1];
    const float* n     = (const float*)d_in[2];
    const float* prior = (const float*)d_in[3];
    const float* w1W = (const float*)d_in[4];  const float* w1b = (const float*)d_in[5];
    const float* b1W = (const float*)d_in[6];  const float* b1b = (const float*)d_in[7];
    const float* w2W = (const float*)d_in[8];  const float* w2b = (const float*)d_in[9];
    const float* b2W = (const float*)d_in[10]; const float* b2b = (const float*)d_in[11];
    const float* w3W = (const float*)d_in[12]; const float* w3b = (const float*)d_in[13];
    const float* b3W = (const float*)d_in[14]; const float* b3b = (const float*)d_in[15];
    float* out = (float*)d_out;

    cudaFuncSetAttribute(min_gemm_hmma_kernel,
                         cudaFuncAttributeMaxDynamicSharedMemorySize, SMEM_TOTAL);

    build_G_kernel<<<dim3((KPAD + 255) / 256, BATCH), 256>>>(
        n, w1W, w1b, b1W, b1b, w2W, w2b, b2W, b2b, w3W, w3b, b3W, b3b);
    split_prior_kernel<<<dim3((KPAD + 255) / 256, BATCH), 256>>>(prior);

    row_norm_kernel<<<BATCH, 256>>>(prior, 0);
    row_norm_kernel<<<BATCH, 256>>>(prior, 1);
    init_min_kernel<<<(BATCH + 255) / 256, 256>>>();

    decode_kernel<<<BATCH, 64>>>(z, znext, out);

    min_gemm_hmma_kernel<<<dim3(BATCH / TN, BATCH / TM), 256, SMEM_TOTAL>>>(0);
    min_gemm_hmma_kernel<<<dim3(BATCH / TN, BATCH / TM), 256, SMEM_TOTAL>>>(1);

    finalize_kernel<<<1, 1024>>>(out);
}

// round 4
// speedup vs baseline: 8.6774x; 1.1889x over previous
#include <cuda_runtime.h>
#include <cuda_fp16.h>
#include <math.h>
#include <stdint.h>

#define BATCH 8192
#define DTOT  4611
#define KPAD  4672              // 73 * 64, zero-padded tail
#define NCHUNK (KPAD / 64)      // 73
#define TM 128
#define TN 256
#define TK 64
#define STAGE_BYTES 49152       // A 16KB + B 32KB
#define SMEM_TOTAL (3 * STAGE_BYTES)

// ---------------- static device scratch -------------------------------------
__device__ float  g_Gf[(size_t)BATCH * DTOT];   // exact fp32 G (decode)
__device__ __half g_Gh[(size_t)BATCH * KPAD];   // fp16 G for MMA
__device__ __half g_Ph[(size_t)BATCH * KPAD];   // fp16 prior for MMA
__device__ float    g_rnG[BATCH];
__device__ float    g_rnP[BATCH];
__device__ unsigned g_minP[BATCH];
__device__ unsigned g_minG[BATCH];
__device__ float    g_recon[BATCH];

// monotone float<->uint key: atomicMin(uint) == min(float), exact+deterministic
__device__ __forceinline__ unsigned fkey(float f) {
    unsigned u = __float_as_uint(f);
    return (u & 0x80000000u) ? ~u : (u | 0x80000000u);
}
__device__ __forceinline__ float funkey(unsigned k) {
    unsigned u = (k & 0x80000000u) ? (k ^ 0x80000000u) : ~k;
    return __uint_as_float(u);
}

__device__ __forceinline__ uint32_t smem_u32(const void* p) {
    uint32_t a;
    asm("{ .reg .u64 t; cvta.to.shared.u64 t, %1; cvt.u32.u64 %0, t; }" : "=r"(a) : "l"(p));
    return a;
}

__device__ __forceinline__ void ldsm_x4(uint32_t& r0, uint32_t& r1, uint32_t& r2,
                                        uint32_t& r3, uint32_t addr) {
    asm volatile("ldmatrix.sync.aligned.m8n8.x4.shared.b16 {%0,%1,%2,%3}, [%4];"
                 : "=r"(r0), "=r"(r1), "=r"(r2), "=r"(r3) : "r"(addr));
}

__device__ __forceinline__ void mma16816(float* d, const uint32_t* a,
                                         uint32_t b0, uint32_t b1) {
    asm volatile("mma.sync.aligned.m16n8k16.row.col.f32.f16.f16.f32 "
                 "{%0,%1,%2,%3}, {%4,%5,%6,%7}, {%8,%9}, {%0,%1,%2,%3};"
                 : "+f"(d[0]), "+f"(d[1]), "+f"(d[2]), "+f"(d[3])
                 : "r"(a[0]), "r"(a[1]), "r"(a[2]), "r"(a[3]), "r"(b0), "r"(b1));
}

// ---------------- phase A: hypernetwork -> fp32 G + fp16 G + norms ----------
// one block per sample row: deterministic in-block norm reduction
__global__ __launch_bounds__(512)
void build_G_kernel(const float* __restrict__ n,
                    const float* __restrict__ w1W, const float* __restrict__ w1b,
                    const float* __restrict__ b1W, const float* __restrict__ b1b,
                    const float* __restrict__ w2W, const float* __restrict__ w2b,
                    const float* __restrict__ b2W, const float* __restrict__ b2b,
                    const float* __restrict__ w3W, const float* __restrict__ w3b,
                    const float* __restrict__ b3W, const float* __restrict__ b3b)
{
    __shared__ float ns[25];
    __shared__ float sm[512];
    const int b = blockIdx.x;
    if (threadIdx.x < 25) ns[threadIdx.x] = n[b * 25 + threadIdx.x];
    __syncthreads();

    float s = 0.f;
    for (int c = threadIdx.x; c < KPAD; c += 512) {
        float val = 0.f;
        if (c < DTOT) {
            const float* W; const float* bias; int local, width;
            if      (c < 192)  { W = w1W; bias = w1b; local = c;        width = 192;  }
            else if (c < 256)  { W = b1W; bias = b1b; local = c - 192;  width = 64;   }
            else if (c < 4352) { W = w2W; bias = w2b; local = c - 256;  width = 4096; }
            else if (c < 4416) { W = b2W; bias = b2b; local = c - 4352; width = 64;   }
            else if (c < 4608) { W = w3W; bias = w3b; local = c - 4416; width = 192;  }
            else               { W = b3W; bias = b3b; local = c - 4608; width = 3;    }
            float acc = 0.f;
            #pragma unroll
            for (int k = 0; k < 25; k++) acc += ns[k] * W[k * width + local];
            val = acc + bias[local];
            g_Gf[(long)b * DTOT + c] = val;
            s += val * val;
        }
        g_Gh[(long)b * KPAD + c] = __float2half_rn(val);
    }
    sm[threadIdx.x] = s;
    __syncthreads();
    for (int off = 256; off > 0; off >>= 1) {
        if (threadIdx.x < off) sm[threadIdx.x] += sm[threadIdx.x + off];
        __syncthreads();
    }
    if (threadIdx.x == 0) g_rnG[b] = sm[0];
}

__global__ __launch_bounds__(256)
void split_prior_kernel(const float* __restrict__ prior)
{
    __shared__ float sm[256];
    const int b = blockIdx.x;
    float s = 0.f;
    for (int c = threadIdx.x; c < KPAD; c += 256) {
        float val = 0.f;
        if (c < DTOT) { val = prior[(long)b * DTOT + c]; s += val * val; }
        g_Ph[(long)b * KPAD + c] = __float2half_rn(val);
    }
    sm[threadIdx.x] = s;
    __syncthreads();
    for (int off = 128; off > 0; off >>= 1) {
        if (threadIdx.x < off) sm[threadIdx.x] += sm[threadIdx.x + off];
        __syncthreads();
    }
    if (threadIdx.x == 0) g_rnP[b] = sm[0];
}

__global__ void init_min_kernel()
{
    int t = blockIdx.x * 256 + threadIdx.x;
    if (t < BATCH) { g_minP[t] = 0xFFFFFFFFu; g_minG[t] = 0xFFFFFFFFu; }
}

// ---------------- phase B: decode MLP (fp32 G) ------------------------------
__global__ void decode_kernel(const float* __restrict__ z,
                              const float* __restrict__ znext,
                              float* __restrict__ out)
{
    const int b = blockIdx.x;
    const float* g = g_Gf + (long)b * DTOT;
    const int i = threadIdx.x;             // 64 threads
    __shared__ float h1[64], h2[64], zh[3];

    const float z0 = z[b * 3], z1 = z[b * 3 + 1], z2 = z[b * 3 + 2];
    float a = g[i * 3] * z0 + g[i * 3 + 1] * z1 + g[i * 3 + 2] * z2 + g[192 + i];
    h1[i] = (a > 0.f) ? a : expm1f(a);
    __syncthreads();

    const float* w2 = g + 256 + i * 64;
    float s = 0.f;
    #pragma unroll 8
    for (int j = 0; j < 64; j++) s += w2[j] * h1[j];
    s += g[4352 + i];
    h2[i] = (s > 0.f) ? s : expm1f(s);
    __syncthreads();

    if (i < 3) {
        const float* w3 = g + 4416 + i * 64;
        float s3 = 0.f;
        #pragma unroll 8
        for (int j = 0; j < 64; j++) s3 += w3[j] * h2[j];
        s3 += g[4608 + i];
        out[2 + b * 3 + i] = s3;
        zh[i] = s3;
    }
    __syncthreads();
    if (i == 0) {
        float d0 = zh[0] - znext[b * 3];
        float d1 = zh[1] - znext[b * 3 + 1];
        float d2 = zh[2] - znext[b * 3 + 2];
        g_recon[b] = d0 * d0 + d1 * d1 + d2 * d2;
    }
}

// ---------------- phase C: HMMA fused GEMM + min ------------------------------
__device__ __forceinline__ void load_tile(uint32_t sbase, const __half* __restrict__ g,
                                          long row0, int k0, int nrows, int tid)
{
    const int nunits = nrows * 8;           // 16B units, 128B per row
    #pragma unroll 4
    for (int u = tid; u < nunits; u += 256) {
        const int r = u >> 3, un = u & 7;
        const int sw = un ^ (r & 7);
        const void* src = g + (row0 + r) * (long)KPAD + k0 + un * 8;
        asm volatile("cp.async.cg.shared.global [%0], [%1], 16;"
                     :: "r"(sbase + (uint32_t)(r * 128 + sw * 16)), "l"(src) : "memory");
    }
}

#define LDF(B, KS)                                                              \
    { _Pragma("unroll") for (int mi = 0; mi < 4; mi++)                          \
        ldsm_x4(afr[B][mi][0], afr[B][mi][1], afr[B][mi][2], afr[B][mi][3],     \
                Ab + aoff[mi] + (uint32_t)((((KS) * 2 + ahalf) ^ asw[mi]) * 16)); \
      _Pragma("unroll") for (int nb = 0; nb < 4; nb++)                          \
        ldsm_x4(bfr[B][nb][0], bfr[B][nb][1], bfr[B][nb][2], bfr[B][nb][3],     \
                Bb + boff[nb] + (uint32_t)((((KS) * 2 + bhalf) ^ bsw[nb]) * 16)); }

#define MMAS(B)                                                                 \
    { _Pragma("unroll") for (int mi = 0; mi < 4; mi++)                          \
      _Pragma("unroll") for (int nb = 0; nb < 4; nb++) {                        \
          mma16816(d[mi][nb * 2],     afr[B][mi], bfr[B][nb][0], bfr[B][nb][1]); \
          mma16816(d[mi][nb * 2 + 1], afr[B][mi], bfr[B][nb][2], bfr[B][nb][3]); } }

// pass 0: A = prior(fp16), colmin[j] = min_i (rnP[i] - 2 P_i.G_j), full grid
// pass 1: A = G, symmetric fold: tiles ib <= 2*jb+1 only; epilogue also
//         folds row-mins (rnG[j] - 2 dot) into colmin[i]. Diagonal masked.
__global__ __launch_bounds__(256, 1)
void min_gemm_hmma_kernel(int pass)
{
    if (pass && (int)blockIdx.y > 2 * (int)blockIdx.x + 1) return;

    const __half* __restrict__ A  = pass ? g_Gh : g_Ph;
    const float* __restrict__ rnA = pass ? g_rnG : g_rnP;
    unsigned* colmin              = pass ? g_minG : g_minP;

    extern __shared__ char smem[];
    const uint32_t sb = smem_u32(smem);
    const int tid = threadIdx.x;
    const int lane = tid & 31;
    const int wid = tid >> 5;
    const int wm = wid >> 2;                 // 0..1  (M)
    const int wn = wid & 3;                  // 0..3  (N)
    const long i0 = (long)blockIdx.y * TM;
    const long j0 = (long)blockIdx.x * TN;

    float d[4][8][4];
    #pragma unroll
    for (int mi = 0; mi < 4; mi++)
        #pragma unroll
        for (int ni = 0; ni < 8; ni++)
            #pragma unroll
            for (int q = 0; q < 4; q++) d[mi][ni][q] = 0.f;

    // per-thread ldmatrix row bases
    int aoff[4], asw[4], boff[4], bsw[4];
    const int ahalf = (lane >> 4) & 1;
    const int bhalf = (lane >> 3) & 1;
    #pragma unroll
    for (int mi = 0; mi < 4; mi++) {
        int row = wm * 64 + mi * 16 + (lane & 7) + ((lane >> 3) & 1) * 8;
        aoff[mi] = row * 128; asw[mi] = row & 7;
    }
    #pragma unroll
    for (int nb = 0; nb < 4; nb++) {
        int row = wn * 64 + nb * 16 + (lane & 7) + ((lane >> 4) & 1) * 8;
        boff[nb] = row * 128; bsw[nb] = row & 7;
    }

    // prologue: chunks 0,1 into stages 0,1
    load_tile(sb,                  A,    i0, 0,  TM, tid);
    load_tile(sb + 16384,          g_Gh, j0, 0,  TN, tid);
    asm volatile("cp.async.commit_group;" ::: "memory");
    load_tile(sb + STAGE_BYTES,          A,    i0, TK, TM, tid);
    load_tile(sb + STAGE_BYTES + 16384,  g_Gh, j0, TK, TN, tid);
    asm volatile("cp.async.commit_group;" ::: "memory");

    int stage = 0, next = 2;
    for (int c = 0; c < NCHUNK; c++) {
        if (c + 2 < NCHUNK) {
            const uint32_t sn = sb + (uint32_t)next * STAGE_BYTES;
            load_tile(sn,         A,    i0, (c + 2) * TK, TM, tid);
            load_tile(sn + 16384, g_Gh, j0, (c + 2) * TK, TN, tid);
            asm volatile("cp.async.commit_group;" ::: "memory");
            asm volatile("cp.async.wait_group 2;" ::: "memory");
        } else if (c + 1 < NCHUNK) {
            asm volatile("cp.async.wait_group 1;" ::: "memory");
        } else {
            asm volatile("cp.async.wait_group 0;" ::: "memory");
        }
        __syncthreads();

        const uint32_t Ab = sb + (uint32_t)stage * STAGE_BYTES;
        const uint32_t Bb = Ab + 16384;

        // double-buffered fragment pipeline over the 4 k16 steps
        uint32_t afr[2][4][4], bfr[2][4][4];
        LDF(0, 0)
        LDF(1, 1)
        MMAS(0)
        LDF(0, 2)
        MMAS(1)
        LDF(1, 3)
        MMAS(0)
        MMAS(1)

        __syncthreads();
        stage = (stage + 1) % 3;
        next  = (next + 1) % 3;
    }

    // ---------------- epilogue ------------------------------------------------
    const int g = lane >> 2, tig = lane & 3;
    float cmin[8][2];
    #pragma unroll
    for (int ni = 0; ni < 8; ni++) { cmin[ni][0] = 1e30f; cmin[ni][1] = 1e30f; }
    float rmin[4][2];
    #pragma unroll
    for (int mi = 0; mi < 4; mi++) { rmin[mi][0] = 1e30f; rmin[mi][1] = 1e30f; }

    // column norms for row-min fold (pass 1 only)
    float rnj0[8], rnj1[8];
    if (pass) {
        #pragma unroll
        for (int ni = 0; ni < 8; ni++) {
            const long jg = j0 + wn * 64 + ni * 8 + 2 * tig;
            rnj0[ni] = g_rnG[jg];
            rnj1[ni] = g_rnG[jg + 1];
        }
    }

    #pragma unroll
    for (int mi = 0; mi < 4; mi++) {
        const long ig0 = i0 + wm * 64 + mi * 16 + g;
        const long ig1 = ig0 + 8;
        const float rn0 = rnA[ig0];
        const float rn1 = rnA[ig1];
        #pragma unroll
        for (int ni = 0; ni < 8; ni++) {
            const float d0 = d[mi][ni][0], d1 = d[mi][ni][1];
            const float d2 = d[mi][ni][2], d3 = d[mi][ni][3];
            float v0 = fmaf(-2.f, d0, rn0);
            float v1 = fmaf(-2.f, d1, rn0);
            float v2 = fmaf(-2.f, d2, rn1);
            float v3 = fmaf(-2.f, d3, rn1);
            if (pass) {
                const long jg = j0 + wn * 64 + ni * 8 + 2 * tig;
                float w0 = fmaf(-2.f, d0, rnj0[ni]);
                float w1 = fmaf(-2.f, d1, rnj1[ni]);
                float w2 = fmaf(-2.f, d2, rnj0[ni]);
                float w3 = fmaf(-2.f, d3, rnj1[ni]);
                if (ig0 == jg)     { v0 = 1e30f; w0 = 1e30f; }
                if (ig0 == jg + 1) { v1 = 1e30f; w1 = 1e30f; }
                if (ig1 == jg)     { v2 = 1e30f; w2 = 1e30f; }
                if (ig1 == jg + 1) { v3 = 1e30f; w3 = 1e30f; }
                rmin[mi][0] = fminf(rmin[mi][0], fminf(w0, w1));
                rmin[mi][1] = fminf(rmin[mi][1], fminf(w2, w3));
            }
            cmin[ni][0] = fminf(cmin[ni][0], fminf(v0, v2));
            cmin[ni][1] = fminf(cmin[ni][1], fminf(v1, v3));
        }
    }

    // column-min: reduce across g-lanes (bits 2..4)
    #pragma unroll
    for (int off = 4; off <= 16; off <<= 1)
        #pragma unroll
        for (int ni = 0; ni < 8; ni++) {
            cmin[ni][0] = fminf(cmin[ni][0], __shfl_xor_sync(0xFFFFFFFFu, cmin[ni][0], off));
            cmin[ni][1] = fminf(cmin[ni][1], __shfl_xor_sync(0xFFFFFFFFu, cmin[ni][1], off));
        }

    float* cbuf = (float*)smem;              // [2][256]
    float* rbuf = cbuf + 512;                // [128][4]
    if (lane < 4) {
        #pragma unroll
        for (int ni = 0; ni < 8; ni++) {
            const int col = wn * 64 + ni * 8 + 2 * lane;
            cbuf[wm * 256 + col]     = cmin[ni][0];
            cbuf[wm * 256 + col + 1] = cmin[ni][1];
        }
    }

    if (pass) {
        // row-min: reduce across tig-lanes (bits 0..1)
        #pragma unroll
        for (int off = 1; off <= 2; off <<= 1)
            #pragma unroll
            for (int mi = 0; mi < 4; mi++) {
                rmin[mi][0] = fminf(rmin[mi][0], __shfl_xor_sync(0xFFFFFFFFu, rmin[mi][0], off));
                rmin[mi][1] = fminf(rmin[mi][1], __shfl_xor_sync(0xFFFFFFFFu, rmin[mi][1], off));
            }
        __syncthreads();          // cbuf/rbuf reuse of stage smem + write ordering
        if (tig == 0) {
            #pragma unroll
            for (int mi = 0; mi < 4; mi++) {
                const int r0 = wm * 64 + mi * 16 + g;
                if (wn == 0) { rbuf[r0 * 4] = rmin[mi][0]; rbuf[(r0 + 8) * 4] = rmin[mi][1]; }
            }
        }
        __syncthreads();
        if (tig == 0 && wn != 0) {
            #pragma unroll
            for (int mi = 0; mi < 4; mi++) {
                const int r0 = wm * 64 + mi * 16 + g;
                rbuf[r0 * 4 + wn]       = rmin[mi][0];
                rbuf[(r0 + 8) * 4 + wn] = rmin[mi][1];
            }
        }
        __syncthreads();
        if (tid < TM) {
            float m = fminf(fminf(rbuf[tid * 4], rbuf[tid * 4 + 1]),
                            fminf(rbuf[tid * 4 + 2], rbuf[tid * 4 + 3]));
            atomicMin(&colmin[i0 + tid], fkey(m));
        }
    } else {
        __syncthreads();
    }

    {
        const float m = fminf(cbuf[tid], cbuf[256 + tid]);
        atomicMin(&colmin[j0 + tid], fkey(m));
    }
}

// ---------------- phase D: final scalar reductions ---------------------------
__global__ void finalize_kernel(float* __restrict__ out)
{
    __shared__ float s1[1024], s2[1024];
    const int t = threadIdx.x;
    float rsum = 0.f, ksum = 0.f;
    for (int j = t; j < BATCH; j += 1024) {
        rsum += g_recon[j];
        float rn = g_rnG[j];
        float wp = sqrtf(fmaxf(funkey(g_minP[j]) + rn, 0.f) + 1e-8f);
        float ww = sqrtf(fmaxf(funkey(g_minG[j]) + rn, 0.f) + 1e-8f);
        ksum += logf(wp / (ww + 1e-8f) + 1e-8f);
    }
    s1[t] = rsum; s2[t] = ksum;
    __syncthreads();
    for (int off = 512; off > 0; off >>= 1) {
        if (t < off) { s1[t] += s1[t + off]; s2[t] += s2[t + off]; }
        __syncthreads();
    }
    if (t == 0) {
        out[0] = s1[0] / (float)BATCH;
        out[1] = s2[0] / (float)BATCH * (float)DTOT
               + logf((float)BATCH / (float)(BATCH - 1));
    }
}

// ---------------- launch ------------------------------------------------------
extern "C" void kernel_launch(void* const* d_in, const int* in_sizes, int n_in,
                              void* d_out, int out_size)
{
    (void)in_sizes; (void)n_in; (void)out_size;
    const float* z     = (const float*)d_in[0];
    const float* znext = (const float*)d_in[1];
    const float* n     = (const float*)d_in[2];
    const float* prior = (const float*)d_in[3];
    const float* w1W = (const float*)d_in[4];  const float* w1b = (const float*)d_in[5];
    const float* b1W = (const float*)d_in[6];  const float* b1b = (const float*)d_in[7];
    const float* w2W = (const float*)d_in[8];  const float* w2b = (const float*)d_in[9];
    const float* b2W = (const float*)d_in[10]; const float* b2b = (const float*)d_in[11];
    const float* w3W = (const float*)d_in[12]; const float* w3b = (const float*)d_in[13];
    const float* b3W = (const float*)d_in[14]; const float* b3b = (const float*)d_in[15];
    float* out = (float*)d_out;

    cudaFuncSetAttribute(min_gemm_hmma_kernel,
                         cudaFuncAttributeMaxDynamicSharedMemorySize, SMEM_TOTAL);

    init_min_kernel<<<(BATCH + 255) / 256, 256>>>();
    build_G_kernel<<<BATCH, 512>>>(
        n, w1W, w1b, b1W, b1b, w2W, w2b, b2W, b2b, w3W, w3b, b3W, b3b);
    split_prior_kernel<<<BATCH, 256>>>(prior);

    decode_kernel<<<BATCH, 64>>>(z, znext, out);

    min_gemm_hmma_kernel<<<dim3(BATCH / TN, BATCH / TM), 256, SMEM_TOTAL>>>(0);
    min_gemm_hmma_kernel<<<dim3(BATCH / TN, BATCH / TM), 256, SMEM_TOTAL>>>(1);

    finalize_kernel<<<1, 1024>>>(out);
}

// round 5
// speedup vs baseline: 9.2399x; 1.0648x over previous
#include <cuda_runtime.h>
#include <cuda_fp16.h>
#include <math.h>
#include <stdint.h>

#define BATCH 8192
#define DTOT  4611
#define KPAD  4672              // 73 * 64, zero-padded tail
#define NCHUNK (KPAD / 64)      // 73
#define TM 128
#define TN 256
#define TK 64
#define NTHR 512
#define STAGE_BYTES 49152       // A 16KB + B 32KB
#define SMEM_TOTAL (3 * STAGE_BYTES)

// ---------------- static device scratch -------------------------------------
__device__ __half g_Gh[(size_t)BATCH * KPAD];   // fp16 G for MMA
__device__ __half g_Ph[(size_t)BATCH * KPAD];   // fp16 prior for MMA
__device__ float    g_rnG[BATCH];
__device__ float    g_rnP[BATCH];
__device__ unsigned g_minP[BATCH];
__device__ unsigned g_minG[BATCH];
__device__ float    g_recon[BATCH];

// monotone float<->uint key: atomicMin(uint) == min(float), exact+deterministic
__device__ __forceinline__ unsigned fkey(float f) {
    unsigned u = __float_as_uint(f);
    return (u & 0x80000000u) ? ~u : (u | 0x80000000u);
}
__device__ __forceinline__ float funkey(unsigned k) {
    unsigned u = (k & 0x80000000u) ? (k ^ 0x80000000u) : ~k;
    return __uint_as_float(u);
}

__device__ __forceinline__ uint32_t smem_u32(const void* p) {
    uint32_t a;
    asm("{ .reg .u64 t; cvta.to.shared.u64 t, %1; cvt.u32.u64 %0, t; }" : "=r"(a) : "l"(p));
    return a;
}

__device__ __forceinline__ void ldsm_x4(uint32_t& r0, uint32_t& r1, uint32_t& r2,
                                        uint32_t& r3, uint32_t addr) {
    asm volatile("ldmatrix.sync.aligned.m8n8.x4.shared.b16 {%0,%1,%2,%3}, [%4];"
                 : "=r"(r0), "=r"(r1), "=r"(r2), "=r"(r3) : "r"(addr));
}

__device__ __forceinline__ void mma16816(float* d, const uint32_t* a,
                                         uint32_t b0, uint32_t b1) {
    asm volatile("mma.sync.aligned.m16n8k16.row.col.f32.f16.f16.f32 "
                 "{%0,%1,%2,%3}, {%4,%5,%6,%7}, {%8,%9}, {%0,%1,%2,%3};"
                 : "+f"(d[0]), "+f"(d[1]), "+f"(d[2]), "+f"(d[3])
                 : "r"(a[0]), "r"(a[1]), "r"(a[2]), "r"(a[3]), "r"(b0), "r"(b1));
}

// ---------------- phase A: hypernetwork + norms + fused decode ---------------
// one block per sample: build G row in smem, write fp16 G, norm-reduce, then
// run the 3-layer decode MLP from smem (no fp32 G round-trip through DRAM).
__global__ __launch_bounds__(512)
void build_G_decode_kernel(const float* __restrict__ n,
                           const float* __restrict__ z,
                           const float* __restrict__ znext,
                           float* __restrict__ out,
                           const float* __restrict__ w1W, const float* __restrict__ w1b,
                           const float* __restrict__ b1W, const float* __restrict__ b1b,
                           const float* __restrict__ w2W, const float* __restrict__ w2b,
                           const float* __restrict__ b2W, const float* __restrict__ b2b,
                           const float* __restrict__ w3W, const float* __restrict__ w3b,
                           const float* __restrict__ b3W, const float* __restrict__ b3b)
{
    __shared__ float ns[25];
    __shared__ float row[KPAD];
    __shared__ float sm[512];
    __shared__ float h1[64], h2[64], zh[3];
    const int b = blockIdx.x;
    const int t = threadIdx.x;
    if (t < 25) ns[t] = n[b * 25 + t];
    __syncthreads();

    float s = 0.f;
    for (int c = t; c < KPAD; c += 512) {
        float val = 0.f;
        if (c < DTOT) {
            const float* W; const float* bias; int local, width;
            if      (c < 192)  { W = w1W; bias = w1b; local = c;        width = 192;  }
            else if (c < 256)  { W = b1W; bias = b1b; local = c - 192;  width = 64;   }
            else if (c < 4352) { W = w2W; bias = w2b; local = c - 256;  width = 4096; }
            else if (c < 4416) { W = b2W; bias = b2b; local = c - 4352; width = 64;   }
            else if (c < 4608) { W = w3W; bias = w3b; local = c - 4416; width = 192;  }
            else               { W = b3W; bias = b3b; local = c - 4608; width = 3;    }
            float acc = 0.f;
            #pragma unroll
            for (int k = 0; k < 25; k++) acc += ns[k] * W[k * width + local];
            val = acc + bias[local];
            s += val * val;
        }
        row[c] = val;
        g_Gh[(long)b * KPAD + c] = __float2half_rn(val);
    }
    sm[t] = s;
    __syncthreads();
    for (int off = 256; off > 0; off >>= 1) {
        if (t < off) sm[t] += sm[t + off];
        __syncthreads();
    }
    if (t == 0) g_rnG[b] = sm[0];

    // ---- decode MLP from smem row (threads 0..63 active) ----
    if (t < 64) {
        const float z0 = z[b * 3], z1 = z[b * 3 + 1], z2 = z[b * 3 + 2];
        float a = row[t * 3] * z0 + row[t * 3 + 1] * z1 + row[t * 3 + 2] * z2
                + row[192 + t];
        h1[t] = (a > 0.f) ? a : expm1f(a);
    }
    __syncthreads();
    if (t < 64) {
        float s2 = 0.f;
        #pragma unroll 8
        for (int jj = 0; jj < 64; jj++) {
            const int j = (jj + t) & 63;                 // bank-rotation
            s2 += row[256 + t * 64 + j] * h1[j];
        }
        s2 += row[4352 + t];
        h2[t] = (s2 > 0.f) ? s2 : expm1f(s2);
    }
    __syncthreads();
    if (t < 3) {
        float s3 = 0.f;
        #pragma unroll 8
        for (int j = 0; j < 64; j++) s3 += row[4416 + t * 64 + j] * h2[j];
        s3 += row[4608 + t];
        out[2 + b * 3 + t] = s3;
        zh[t] = s3;
    }
    __syncthreads();
    if (t == 0) {
        float d0 = zh[0] - znext[b * 3];
        float d1 = zh[1] - znext[b * 3 + 1];
        float d2 = zh[2] - znext[b * 3 + 2];
        g_recon[b] = d0 * d0 + d1 * d1 + d2 * d2;
    }
}

__global__ __launch_bounds__(256)
void split_prior_kernel(const float* __restrict__ prior)
{
    __shared__ float sm[256];
    const int b = blockIdx.x;
    float s = 0.f;
    for (int c = threadIdx.x; c < KPAD; c += 256) {
        float val = 0.f;
        if (c < DTOT) { val = prior[(long)b * DTOT + c]; s += val * val; }
        g_Ph[(long)b * KPAD + c] = __float2half_rn(val);
    }
    sm[threadIdx.x] = s;
    __syncthreads();
    for (int off = 128; off > 0; off >>= 1) {
        if (threadIdx.x < off) sm[threadIdx.x] += sm[threadIdx.x + off];
        __syncthreads();
    }
    if (threadIdx.x == 0) g_rnP[b] = sm[0];
}

__global__ void init_min_kernel()
{
    int t = blockIdx.x * 256 + threadIdx.x;
    if (t < BATCH) { g_minP[t] = 0xFFFFFFFFu; g_minG[t] = 0xFFFFFFFFu; }
}

// ---------------- phase C: HMMA fused GEMM + min ------------------------------
__device__ __forceinline__ void load_tile(uint32_t sbase, const __half* __restrict__ g,
                                          long row0, int k0, int nrows, int tid)
{
    const int nunits = nrows * 8;           // 16B units, 128B per row
    #pragma unroll 4
    for (int u = tid; u < nunits; u += NTHR) {
        const int r = u >> 3, un = u & 7;
        const int sw = un ^ (r & 7);
        const void* src = g + (row0 + r) * (long)KPAD + k0 + un * 8;
        asm volatile("cp.async.cg.shared.global [%0], [%1], 16;"
                     :: "r"(sbase + (uint32_t)(r * 128 + sw * 16)), "l"(src) : "memory");
    }
}

// pass 0: A = prior(fp16), colmin[j] = min_i (rnP[i] - 2 P_i.G_j), full grid
// pass 1: A = G, symmetric fold: tiles ib <= 2*jb+1 only; epilogue also
//         folds row-mins (rnG[j] - 2 dot) into colmin[i]. Diagonal masked.
__global__ __launch_bounds__(NTHR, 1)
void min_gemm_hmma_kernel(int pass)
{
    if (pass && (int)blockIdx.y > 2 * (int)blockIdx.x + 1) return;

    const __half* __restrict__ A  = pass ? g_Gh : g_Ph;
    const float* __restrict__ rnA = pass ? g_rnG : g_rnP;
    unsigned* colmin              = pass ? g_minG : g_minP;

    extern __shared__ char smem[];
    const uint32_t sb = smem_u32(smem);
    const int tid = threadIdx.x;
    const int lane = tid & 31;
    const int wid = tid >> 5;                // 0..15
    const int wm = wid >> 2;                 // 0..3  (M, 32 rows each)
    const int wn = wid & 3;                  // 0..3  (N, 64 cols each)
    const long i0 = (long)blockIdx.y * TM;
    const long j0 = (long)blockIdx.x * TN;

    float d[2][8][4];
    #pragma unroll
    for (int mi = 0; mi < 2; mi++)
        #pragma unroll
        for (int ni = 0; ni < 8; ni++)
            #pragma unroll
            for (int q = 0; q < 4; q++) d[mi][ni][q] = 0.f;

    // per-thread ldmatrix row bases
    int aoff[2], asw[2], boff[4], bsw[4];
    const int ahalf = (lane >> 4) & 1;
    const int bhalf = (lane >> 3) & 1;
    #pragma unroll
    for (int mi = 0; mi < 2; mi++) {
        int row = wm * 32 + mi * 16 + (lane & 7) + ((lane >> 3) & 1) * 8;
        aoff[mi] = row * 128; asw[mi] = row & 7;
    }
    #pragma unroll
    for (int nb = 0; nb < 4; nb++) {
        int row = wn * 64 + nb * 16 + (lane & 7) + ((lane >> 4) & 1) * 8;
        boff[nb] = row * 128; bsw[nb] = row & 7;
    }

    // prologue: chunks 0,1 into stages 0,1
    load_tile(sb,                  A,    i0, 0,  TM, tid);
    load_tile(sb + 16384,          g_Gh, j0, 0,  TN, tid);
    asm volatile("cp.async.commit_group;" ::: "memory");
    load_tile(sb + STAGE_BYTES,          A,    i0, TK, TM, tid);
    load_tile(sb + STAGE_BYTES + 16384,  g_Gh, j0, TK, TN, tid);
    asm volatile("cp.async.commit_group;" ::: "memory");

    int stage = 0, next = 2;
    for (int c = 0; c < NCHUNK; c++) {
        if (c + 2 < NCHUNK) {
            const uint32_t sn = sb + (uint32_t)next * STAGE_BYTES;
            load_tile(sn,         A,    i0, (c + 2) * TK, TM, tid);
            load_tile(sn + 16384, g_Gh, j0, (c + 2) * TK, TN, tid);
            asm volatile("cp.async.commit_group;" ::: "memory");
            asm volatile("cp.async.wait_group 2;" ::: "memory");
        } else if (c + 1 < NCHUNK) {
            asm volatile("cp.async.wait_group 1;" ::: "memory");
        } else {
            asm volatile("cp.async.wait_group 0;" ::: "memory");
        }
        __syncthreads();

        const uint32_t Ab = sb + (uint32_t)stage * STAGE_BYTES;
        const uint32_t Bb = Ab + 16384;

        #pragma unroll
        for (int ks = 0; ks < 4; ks++) {
            uint32_t a[2][4], b[4][4];
            #pragma unroll
            for (int mi = 0; mi < 2; mi++)
                ldsm_x4(a[mi][0], a[mi][1], a[mi][2], a[mi][3],
                        Ab + aoff[mi] + (uint32_t)(((ks * 2 + ahalf) ^ asw[mi]) * 16));
            #pragma unroll
            for (int nb = 0; nb < 4; nb++)
                ldsm_x4(b[nb][0], b[nb][1], b[nb][2], b[nb][3],
                        Bb + boff[nb] + (uint32_t)(((ks * 2 + bhalf) ^ bsw[nb]) * 16));
            #pragma unroll
            for (int mi = 0; mi < 2; mi++)
                #pragma unroll
                for (int nb = 0; nb < 4; nb++) {
                    mma16816(d[mi][nb * 2],     a[mi], b[nb][0], b[nb][1]);
                    mma16816(d[mi][nb * 2 + 1], a[mi], b[nb][2], b[nb][3]);
                }
        }
        __syncthreads();
        stage = (stage + 1) % 3;
        next  = (next + 1) % 3;
    }

    // ---------------- epilogue ------------------------------------------------
    const int g = lane >> 2, tig = lane & 3;
    float cmin[8][2];
    #pragma unroll
    for (int ni = 0; ni < 8; ni++) { cmin[ni][0] = 1e30f; cmin[ni][1] = 1e30f; }
    float rmin[2][2];
    #pragma unroll
    for (int mi = 0; mi < 2; mi++) { rmin[mi][0] = 1e30f; rmin[mi][1] = 1e30f; }

    float rnj0[8], rnj1[8];
    if (pass) {
        #pragma unroll
        for (int ni = 0; ni < 8; ni++) {
            const long jg = j0 + wn * 64 + ni * 8 + 2 * tig;
            rnj0[ni] = g_rnG[jg];
            rnj1[ni] = g_rnG[jg + 1];
        }
    }

    #pragma unroll
    for (int mi = 0; mi < 2; mi++) {
        const long ig0 = i0 + wm * 32 + mi * 16 + g;
        const long ig1 = ig0 + 8;
        const float rn0 = rnA[ig0];
        const float rn1 = rnA[ig1];
        #pragma unroll
        for (int ni = 0; ni < 8; ni++) {
            const float d0 = d[mi][ni][0], d1 = d[mi][ni][1];
            const float d2 = d[mi][ni][2], d3 = d[mi][ni][3];
            float v0 = fmaf(-2.f, d0, rn0);
            float v1 = fmaf(-2.f, d1, rn0);
            float v2 = fmaf(-2.f, d2, rn1);
            float v3 = fmaf(-2.f, d3, rn1);
            if (pass) {
                const long jg = j0 + wn * 64 + ni * 8 + 2 * tig;
                float w0 = fmaf(-2.f, d0, rnj0[ni]);
                float w1 = fmaf(-2.f, d1, rnj1[ni]);
                float w2 = fmaf(-2.f, d2, rnj0[ni]);
                float w3 = fmaf(-2.f, d3, rnj1[ni]);
                if (ig0 == jg)     { v0 = 1e30f; w0 = 1e30f; }
                if (ig0 == jg + 1) { v1 = 1e30f; w1 = 1e30f; }
                if (ig1 == jg)     { v2 = 1e30f; w2 = 1e30f; }
                if (ig1 == jg + 1) { v3 = 1e30f; w3 = 1e30f; }
                rmin[mi][0] = fminf(rmin[mi][0], fminf(w0, w1));
                rmin[mi][1] = fminf(rmin[mi][1], fminf(w2, w3));
            }
            cmin[ni][0] = fminf(cmin[ni][0], fminf(v0, v2));
            cmin[ni][1] = fminf(cmin[ni][1], fminf(v1, v3));
        }
    }

    // column-min: reduce across g-lanes (bits 2..4)
    #pragma unroll
    for (int off = 4; off <= 16; off <<= 1)
        #pragma unroll
        for (int ni = 0; ni < 8; ni++) {
            cmin[ni][0] = fminf(cmin[ni][0], __shfl_xor_sync(0xFFFFFFFFu, cmin[ni][0], off));
            cmin[ni][1] = fminf(cmin[ni][1], __shfl_xor_sync(0xFFFFFFFFu, cmin[ni][1], off));
        }
    if (pass) {
        // row-min: reduce across tig-lanes (bits 0..1)
        #pragma unroll
        for (int off = 1; off <= 2; off <<= 1)
            #pragma unroll
            for (int mi = 0; mi < 2; mi++) {
                rmin[mi][0] = fminf(rmin[mi][0], __shfl_xor_sync(0xFFFFFFFFu, rmin[mi][0], off));
                rmin[mi][1] = fminf(rmin[mi][1], __shfl_xor_sync(0xFFFFFFFFu, rmin[mi][1], off));
            }
    }

    float* cbuf = (float*)smem;              // [4][256]
    float* rbuf = cbuf + 1024;               // [128][4]
    if (lane < 4) {
        #pragma unroll
        for (int ni = 0; ni < 8; ni++) {
            const int col = wn * 64 + ni * 8 + 2 * lane;
            cbuf[wm * 256 + col]     = cmin[ni][0];
            cbuf[wm * 256 + col + 1] = cmin[ni][1];
        }
    }
    if (pass && tig == 0) {
        #pragma unroll
        for (int mi = 0; mi < 2; mi++) {
            const int r0 = wm * 32 + mi * 16 + g;     // unique (r, wn) per writer
            rbuf[r0 * 4 + wn]       = rmin[mi][0];
            rbuf[(r0 + 8) * 4 + wn] = rmin[mi][1];
        }
    }
    __syncthreads();

    if (tid < TN) {
        const float m = fminf(fminf(cbuf[tid], cbuf[256 + tid]),
                              fminf(cbuf[512 + tid], cbuf[768 + tid]));
        atomicMin(&colmin[j0 + tid], fkey(m));
    }
    if (pass && tid >= TN && tid < TN + TM) {
        const int r = tid - TN;
        const float m = fminf(fminf(rbuf[r * 4], rbuf[r * 4 + 1]),
                              fminf(rbuf[r * 4 + 2], rbuf[r * 4 + 3]));
        atomicMin(&colmin[i0 + r], fkey(m));
    }
}

// ---------------- phase D: final scalar reductions ---------------------------
__global__ void finalize_kernel(float* __restrict__ out)
{
    __shared__ float s1[1024], s2[1024];
    const int t = threadIdx.x;
    float rsum = 0.f, ksum = 0.f;
    for (int j = t; j < BATCH; j += 1024) {
        rsum += g_recon[j];
        float rn = g_rnG[j];
        float wp = sqrtf(fmaxf(funkey(g_minP[j]) + rn, 0.f) + 1e-8f);
        float ww = sqrtf(fmaxf(funkey(g_minG[j]) + rn, 0.f) + 1e-8f);
        ksum += logf(wp / (ww + 1e-8f) + 1e-8f);
    }
    s1[t] = rsum; s2[t] = ksum;
    __syncthreads();
    for (int off = 512; off > 0; off >>= 1) {
        if (t < off) { s1[t] += s1[t + off]; s2[t] += s2[t + off]; }
        __syncthreads();
    }
    if (t == 0) {
        out[0] = s1[0] / (float)BATCH;
        out[1] = s2[0] / (float)BATCH * (float)DTOT
               + logf((float)BATCH / (float)(BATCH - 1));
    }
}

// ---------------- launch ------------------------------------------------------
extern "C" void kernel_launch(void* const* d_in, const int* in_sizes, int n_in,
                              void* d_out, int out_size)
{
    (void)in_sizes; (void)n_in; (void)out_size;
    const float* z     = (const float*)d_in[0];
    const float* znext = (const float*)d_in[1];
    const float* n     = (const float*)d_in[2];
    const float* prior = (const float*)d_in[3];
    const float* w1W = (const float*)d_in[4];  const float* w1b = (const float*)d_in[5];
    const float* b1W = (const float*)d_in[6];  const float* b1b = (const float*)d_in[7];
    const float* w2W = (const float*)d_in[8];  const float* w2b = (const float*)d_in[9];
    const float* b2W = (const float*)d_in[10]; const float* b2b = (const float*)d_in[11];
    const float* w3W = (const float*)d_in[12]; const float* w3b = (const float*)d_in[13];
    const float* b3W = (const float*)d_in[14]; const float* b3b = (const float*)d_in[15];
    float* out = (float*)d_out;

    cudaFuncSetAttribute(min_gemm_hmma_kernel,
                         cudaFuncAttributeMaxDynamicSharedMemorySize, SMEM_TOTAL);

    init_min_kernel<<<(BATCH + 255) / 256, 256>>>();
    build_G_decode_kernel<<<BATCH, 512>>>(
        n, z, znext, out,
        w1W, w1b, b1W, b1b, w2W, w2b, b2W, b2b, w3W, w3b, b3W, b3b);
    split_prior_kernel<<<BATCH, 256>>>(prior);

    min_gemm_hmma_kernel<<<dim3(BATCH / TN, BATCH / TM), NTHR, SMEM_TOTAL>>>(0);
    min_gemm_hmma_kernel<<<dim3(BATCH / TN, BATCH / TM), NTHR, SMEM_TOTAL>>>(1);

    finalize_kernel<<<1, 1024>>>(out);
}